// round 11
// baseline (speedup 1.0000x reference)
#include <cuda_runtime.h>
#include <cstdint>
#include <cstddef>

// Problem constants (fixed by the dataset)
#define Bn   8
#define Tn   128
#define Un   64
#define U1n  65          // U+1
#define Vn   1024
// blank = V-1 (last class)

#define DDn  208         // padded diagonal count (max dd=190, prefetch reads to +8)
#define Wn   66          // padded diagonal width (u: 0..65)
#define GRP  8           // DP prefetch depth (diagonals)

#define LOG2E 1.4426950408889634f
#define LN2   0.6931471805599453f

// DIAGONAL-MAJOR scratch (base-2 log domain):
//   gD_blank[b][dd][u]   = lp2_blank(t,u),  dd = t+u
//   gD_emit [b][dd][u+1] = lp2_emit (t,u),  dd = t+u   (shifted +1 so a float2
//                          at [2l] yields (emit[2l-1], emit[2l]) per lane)
__device__ __align__(16) float gD_blank[Bn * DDn * Wn];
__device__ __align__(16) float gD_emit [Bn * DDn * Wn];
__device__ int g_diag_ready[Bn * DDn];   // #completed lse warps per (b, diagonal)

__device__ __forceinline__ float neg_inf() { return __int_as_float(0xff800000u); }

// Base-2 logaddexp via EX2 + deg-5 poly for log2(1+y); P(0)=0 keeps -inf algebra
// NaN-free (z clamped to -45 handles the both--inf NaN).
__device__ __forceinline__ float lae2p(float va, float vb) {
    const float C1 =  1.4419672f;
    const float C2 = -0.7096747f;
    const float C3 =  0.4176170f;
    const float C4 = -0.1962970f;
    const float C5 =  0.0463940f;
    float mx = fmaxf(va, vb);
    float mn = fminf(va, vb);
    float z  = fmaxf(mn - mx, -45.0f);
    float y;
    asm("ex2.approx.ftz.f32 %0, %1;" : "=f"(y) : "f"(z));
    float g = y * (C1 + y * (C2 + y * (C3 + y * (C4 + y * C5))));
    return mx + g;
}

// ---------------------------------------------------------------------------
__global__ void init_kernel() {
    int i = blockIdx.x * 256 + threadIdx.x;
    if (i < Bn * DDn) g_diag_ready[i] = 0;
}

// ---------------------------------------------------------------------------
// Fused kernel.
//  blocks 0..7        : DP (warp0 = wavefront DP, warp1 = readiness poller)
//  blocks 8..8327     : lse rows, one warp per (b,t,u); publish via release-add
// ---------------------------------------------------------------------------
__global__ void __launch_bounds__(256) fused_kernel(
    const float* __restrict__ logits,
    const int*   __restrict__ targets,
    const int*   __restrict__ logit_lengths,
    const int*   __restrict__ target_lengths,
    float*       __restrict__ out)
{
    // ======================= DP blocks =======================
    if (blockIdx.x < Bn) {
        __shared__ int s_wm;                 // highest fully-ready diagonal
        if (threadIdx.x == 0) s_wm = -1;
        __syncthreads();

        int b    = blockIdx.x;
        int wib  = threadIdx.x >> 5;
        int lane = threadIdx.x & 31;
        if (wib >= 2) return;

        int Tl = logit_lengths[b];
        int Ul = target_lengths[b];
        const int t_last = Tl - 1;
        const int u_last = Ul;
        const int d_end  = t_last + u_last;

        if (wib == 1) {
            // -------- poller: advance watermark, 32 diagonals per probe --------
            int w = -1;
            const int* cnt = g_diag_ready + b * DDn;
            while (w < d_end) {
                int dd = w + 1 + lane;
                int ok;
                if (dd <= d_end) {
                    int lo = max(0, dd - Ul);
                    int hi = min(t_last, dd);
                    int expect = hi - lo + 1;
                    int c;
                    asm volatile("ld.acquire.gpu.global.b32 %0, [%1];"
                                 : "=r"(c) : "l"(cnt + dd) : "memory");
                    ok = (c >= expect);
                } else ok = 1;
                unsigned bal = __ballot_sync(0xffffffffu, ok);
                int adv = (~bal == 0u) ? 32 : (__ffs(~bal) - 1);
                if (adv > 0) {
                    w += adv;
                    if (lane == 0) {
                        __threadfence_block();
                        *(volatile int*)&s_wm = w;
                    }
                } else {
                    __nanosleep(200);
                }
            }
            return;
        }

        // ---------------- DP warp ----------------
        const float NEG = neg_inf();
        const float* dbBase = gD_blank + b * DDn * Wn;
        const float* deBase = gD_emit  + b * DDn * Wn;
        const int src = (lane + 31) & 31;
        const bool l0 = (lane == 0);

        int wm_cache = -1;
        auto wait_wm = [&](int need) {
            if (wm_cache >= need) return;
            int v;
            do { v = *(volatile int*)&s_wm; } while (v < need);
            wm_cache = v;
            __threadfence_block();
        };

        float2 BA[GRP], EA[GRP];
        float  BU[GRP], EU[GRP];

        // Prologue: diagonals 0..GRP-1 feed iterations d = 1..GRP.
        wait_wm(min(GRP - 1, d_end));
#pragma unroll
        for (int k = 0; k < GRP; k++) {
            const float* pB = dbBase + k * Wn;
            const float* pE = deBase + k * Wn;
            BA[k] = *(const float2*)(pB + 2 * lane);
            EA[k] = *(const float2*)(pE + 2 * lane);
            BU[k] = pB[64];
            EU[k] = pE[64];
        }

        // Diagonal d = 0: only cell (0,0) (lane0 slot0) = 0.
        float p0 = l0 ? 0.0f : NEG;
        float p1 = NEG, p2 = NEG;
        float f0 = NEG, f1 = NEG, f2 = NEG;   // snapshot at d == d_end

        for (int g = 1; g <= d_end; g += GRP) {
            // Next group's prefetches touch diagonals up to g+2*GRP-2.
            wait_wm(min(g + 2 * GRP - 2, d_end));
#pragma unroll
            for (int k = 0; k < GRP; k++) {
                int d = g + k;
                float s1 = __shfl_sync(0xffffffffu, p1, src);

                float blk0 = BA[k].x, blk1 = BA[k].y, blk2 = BU[k];
                float emt0 = EA[k].x, emt1 = EA[k].y, emt2 = EU[k];

                // Prefetch diagonal d+GRP-1 (for iteration d+GRP) into slot k.
                {
                    int dd = g + k + GRP - 1;
                    const float* pB = dbBase + dd * Wn;
                    const float* pE = deBase + dd * Wn;
                    BA[k] = *(const float2*)(pB + 2 * lane);
                    EA[k] = *(const float2*)(pE + 2 * lane);
                    BU[k] = pB[64];
                    EU[k] = pE[64];
                }

                float nb0 = l0 ? NEG : s1;   // u=2l: left parent = lane l-1 odd col
                float nb1 = p0;              // u=2l+1: left parent local (prev diag)
                float nb2 = p1;              // u=64: left parent = lane31 slot1

                float q0 = lae2p(p0 + blk0, nb0 + emt0);
                float q1 = lae2p(p1 + blk1, nb1 + emt1);
                float q2 = lae2p(p2 + blk2, nb2 + emt2);

                bool last = (d == d_end);
                f0 = last ? q0 : f0;
                f1 = last ? q1 : f1;
                f2 = last ? q2 : f2;

                p0 = q0; p1 = q1; p2 = q2;
            }
        }

        // Extract alpha[t_last][u_last] from snapshot of diagonal d_end.
        float af;
        if (u_last == 64)    af = __shfl_sync(0xffffffffu, f2, 31);
        else if (u_last & 1) af = __shfl_sync(0xffffffffu, f1, u_last >> 1);
        else                 af = __shfl_sync(0xffffffffu, f0, u_last >> 1);

        // final blank lp2 at (t_last, u_last): diag d_end, col u_last (ready).
        float fb = dbBase[d_end * Wn + u_last];

        if (lane == 0) out[b] = -(af + fb) * LN2;
        return;
    }

    // ======================= lse blocks =======================
    int warp = (int)((blockIdx.x - Bn) * 8 + (threadIdx.x >> 5));
    int lane = threadIdx.x & 31;
    if (warp >= Bn * Tn * U1n) return;

    int b   = warp / (Tn * U1n);
    int rem = warp - b * (Tn * U1n);
    int t   = rem / U1n;
    int u   = rem - t * U1n;

    int Tl = logit_lengths[b];
    int Ul = target_lengths[b];
    if (t >= Tl || u > Ul) return;   // never read by the DP

    const float4* row = reinterpret_cast<const float4*>(logits) + (size_t)warp * (Vn / 4);
    float4 v[8];
#pragma unroll
    for (int j = 0; j < 8; j++) v[j] = row[j * 32 + lane];

    float m = v[0].x;
#pragma unroll
    for (int j = 0; j < 8; j++) {
        m = fmaxf(m, v[j].x); m = fmaxf(m, v[j].y);
        m = fmaxf(m, v[j].z); m = fmaxf(m, v[j].w);
    }
    float s = 0.0f;
#pragma unroll
    for (int j = 0; j < 8; j++) {
        s += __expf(v[j].x - m); s += __expf(v[j].y - m);
        s += __expf(v[j].z - m); s += __expf(v[j].w - m);
    }

    // blank class = V-1: lives in v[7].w of lane 31.
    float blankv = __shfl_sync(0xffffffffu, v[7].w, 31);

#pragma unroll
    for (int off = 16; off; off >>= 1) {
        float om = __shfl_xor_sync(0xffffffffu, m, off);
        float os = __shfl_xor_sync(0xffffffffu, s, off);
        float nm = fmaxf(m, om);
        s = s * __expf(m - nm) + os * __expf(om - nm);
        m = nm;
    }
    float lse = m + __logf(s);

    if (lane == 0) {
        int dd = t + u;
        float* dstB = gD_blank + (b * DDn + dd) * Wn + u;
        *dstB = (blankv - lse) * LOG2E;
        if (u < Ul) {
            int tgt = targets[b * Un + u];
            gD_emit[(b * DDn + dd) * Wn + (u + 1)] =
                (logits[(size_t)warp * Vn + tgt] - lse) * LOG2E;
        }
        // Publish: release-ordered increment of this diagonal's counter.
        asm volatile("red.release.gpu.global.add.u32 [%0], 1;"
                     :: "l"(g_diag_ready + b * DDn + dd) : "memory");
    }
}

// ---------------------------------------------------------------------------
extern "C" void kernel_launch(void* const* d_in, const int* in_sizes, int n_in,
                              void* d_out, int out_size)
{
    const float* logits         = (const float*)d_in[0];
    const int*   targets        = (const int*)  d_in[1];
    const int*   logit_lengths  = (const int*)  d_in[2];
    const int*   target_lengths = (const int*)  d_in[3];
    float*       out            = (float*)      d_out;

    int rows       = Bn * Tn * U1n;                 // 66560 rows -> one warp each
    int lse_blocks = (rows + 7) / 8;                // 8320 blocks of 8 warps
    int blocks     = Bn + lse_blocks;               // DP blocks first (resident early)

    init_kernel<<<(Bn * DDn + 255) / 256, 256>>>();
    fused_kernel<<<blocks, 256>>>(logits, targets, logit_lengths, target_lengths, out);
}

// round 13
// speedup vs baseline: 1.2483x; 1.2483x over previous
#include <cuda_runtime.h>
#include <cstdint>
#include <cstddef>

// Problem constants (fixed by the dataset)
#define Bn   8
#define Tn   128
#define Un   64
#define U1n  65          // U+1
#define Vn   1024
// blank = V-1 (last class)

#define DDn  208         // padded diagonal count (max dd=190; prefetch reads to +2*GRP)
#define Wn   66          // padded diagonal width (u: 0..65)
#define GRP  4           // DP prefetch depth (diagonals)

#define LOG2E 1.4426950408889634f
#define LN2   0.6931471805599453f

// DIAGONAL-MAJOR scratch (base-2 log domain):
//   gD_blank[b][dd][u]   = lp2_blank(t,u),  dd = t+u
//   gD_emit [b][dd][u+1] = lp2_emit (t,u),  dd = t+u   (+1 shift so a float2 at
//                          [2l] yields (emit[.,2l-1], emit[.,2l]) per lane)
__device__ __align__(16) float gD_blank[Bn * DDn * Wn];
__device__ __align__(16) float gD_emit [Bn * DDn * Wn];
__device__ int g_diag_ready[Bn * DDn];   // #completed lse warps per (b, diagonal)

__device__ __forceinline__ float neg_inf() { return __int_as_float(0xff800000u); }

// Base-2 logaddexp via EX2 + deg-5 poly for log2(1+y); P(0)=0 keeps -inf algebra
// NaN-free (z clamped to -45 handles the both--inf NaN).
__device__ __forceinline__ float lae2p(float va, float vb) {
    const float C1 =  1.4419672f;
    const float C2 = -0.7096747f;
    const float C3 =  0.4176170f;
    const float C4 = -0.1962970f;
    const float C5 =  0.0463940f;
    float mx = fmaxf(va, vb);
    float mn = fminf(va, vb);
    float z  = fmaxf(mn - mx, -45.0f);
    float y;
    asm("ex2.approx.ftz.f32 %0, %1;" : "=f"(y) : "f"(z));
    float g = y * (C1 + y * (C2 + y * (C3 + y * (C4 + y * C5))));
    return mx + g;
}

// ---------------------------------------------------------------------------
__global__ void init_kernel() {
    int i = blockIdx.x * 256 + threadIdx.x;
    if (i < Bn * DDn) g_diag_ready[i] = 0;
}

// Decode j in [0, 8320) -> (dd, u) enumerating the 128 x 65 grid by
// anti-diagonal dd = t+u in increasing order. Region A: dd 0..64 (len dd+1),
// region B: dd 65..127 (len 65), region C: dd 128..191 (len 192-dd).
__device__ __forceinline__ void diag_decode(int j, int& dd, int& u) {
    if (j < 2145) {                                  // region A
        int q = (int)((sqrtf(8.0f * (float)j + 1.0f) - 1.0f) * 0.5f);
        while ((q + 1) * (q + 2) / 2 <= j) q++;
        while (q * (q + 1) / 2 > j) q--;
        dd = q;
        u  = j - q * (q + 1) / 2;
    } else if (j < 6240) {                           // region B
        int j2 = j - 2145;
        dd = 65 + j2 / 65;
        u  = j2 - (dd - 65) * 65;
    } else {                                         // region C (reverse ramp)
        int r = 2079 - (j - 6240);                   // reversed index, len 1,2,..,64
        int q = (int)((sqrtf(8.0f * (float)r + 1.0f) - 1.0f) * 0.5f);
        while ((q + 1) * (q + 2) / 2 <= r) q++;
        while (q * (q + 1) / 2 > r) q--;
        int s = r - q * (q + 1) / 2;                 // 0..q
        dd = 191 - q;
        u  = (dd - 127) + (q - s);
    }
}

// ---------------------------------------------------------------------------
// Fused kernel (single stream, graph-friendly).
//  blocks 0..7   : DP (warp0 = wavefront DP, warp1 = watermark poller)
//  blocks 8..    : lse rows in DIAGONAL-MAJOR, BATCH-INTERLEAVED order, so all
//                  batches' low diagonals are produced first and every DP block
//                  rides ~1 diagonal behind the producer.
// __launch_bounds__(256,5) caps regs (~48) so lse keeps high occupancy (the
// R11 failure was an 80-reg unified allocation).
// ---------------------------------------------------------------------------
__global__ void __launch_bounds__(256, 5) fused_kernel(
    const float* __restrict__ logits,
    const int*   __restrict__ targets,
    const int*   __restrict__ logit_lengths,
    const int*   __restrict__ target_lengths,
    float*       __restrict__ out)
{
    // ======================= DP blocks =======================
    if (blockIdx.x < Bn) {
        __shared__ int s_wm;                 // highest fully-ready diagonal
        if (threadIdx.x == 0) s_wm = -1;
        __syncthreads();

        int b    = blockIdx.x;
        int wib  = threadIdx.x >> 5;
        int lane = threadIdx.x & 31;
        if (wib >= 2) return;

        int Tl = logit_lengths[b];
        int Ul = target_lengths[b];
        const int t_last = Tl - 1;
        const int u_last = Ul;
        const int d_end  = t_last + u_last;

        if (wib == 1) {
            // -------- poller: advance watermark, 32 diagonals per probe --------
            int w = -1;
            const int* cnt = g_diag_ready + b * DDn;
            while (w < d_end) {
                int dd = w + 1 + lane;
                int ok;
                if (dd <= d_end) {
                    int lo = max(0, dd - Ul);
                    int hi = min(t_last, dd);
                    int expect = hi - lo + 1;
                    int c;
                    asm volatile("ld.acquire.gpu.global.b32 %0, [%1];"
                                 : "=r"(c) : "l"(cnt + dd) : "memory");
                    ok = (c >= expect);
                } else ok = 1;
                unsigned bal = __ballot_sync(0xffffffffu, ok);
                int adv = (~bal == 0u) ? 32 : (__ffs(~bal) - 1);
                if (adv > 0) {
                    w += adv;
                    if (lane == 0) {
                        __threadfence_block();
                        *(volatile int*)&s_wm = w;
                    }
                } else {
                    __nanosleep(200);
                }
            }
            return;
        }

        // ---------------- DP warp ----------------
        const float NEG = neg_inf();
        const float* dbBase = gD_blank + b * DDn * Wn;
        const float* deBase = gD_emit  + b * DDn * Wn;
        const int src = (lane + 31) & 31;
        const bool l0 = (lane == 0);

        int wm_cache = -1;
        auto wait_wm = [&](int need) {
            if (wm_cache >= need) return;
            int v;
            do { v = *(volatile int*)&s_wm; } while (v < need);
            wm_cache = v;
            __threadfence_block();
        };

        float2 BA[GRP], EA[GRP];
        float  BU[GRP], EU[GRP];

        // Prologue: diagonals 0..GRP-1 feed iterations d = 1..GRP.
        wait_wm(min(GRP - 1, d_end));
#pragma unroll
        for (int k = 0; k < GRP; k++) {
            const float* pB = dbBase + k * Wn;
            const float* pE = deBase + k * Wn;
            BA[k] = *(const float2*)(pB + 2 * lane);
            EA[k] = *(const float2*)(pE + 2 * lane);
            BU[k] = pB[64];
            EU[k] = pE[64];
        }

        // Diagonal d = 0: only cell (0,0) (lane0 slot0) = 0.
        float p0 = l0 ? 0.0f : NEG;
        float p1 = NEG, p2 = NEG;
        float f0 = NEG, f1 = NEG, f2 = NEG;   // snapshot at d == d_end

        for (int g = 1; g <= d_end; g += GRP) {
            // Next group's prefetches touch diagonals up to g+2*GRP-2.
            wait_wm(min(g + 2 * GRP - 2, d_end));
#pragma unroll
            for (int k = 0; k < GRP; k++) {
                int d = g + k;
                float s1 = __shfl_sync(0xffffffffu, p1, src);

                float blk0 = BA[k].x, blk1 = BA[k].y, blk2 = BU[k];
                float emt0 = EA[k].x, emt1 = EA[k].y, emt2 = EU[k];

                // Prefetch diagonal d+GRP-1 (for iteration d+GRP) into slot k.
                {
                    int dd = g + k + GRP - 1;
                    const float* pB = dbBase + dd * Wn;
                    const float* pE = deBase + dd * Wn;
                    BA[k] = *(const float2*)(pB + 2 * lane);
                    EA[k] = *(const float2*)(pE + 2 * lane);
                    BU[k] = pB[64];
                    EU[k] = pE[64];
                }

                float nb0 = l0 ? NEG : s1;   // u=2l: left parent = lane l-1 odd col
                float nb1 = p0;              // u=2l+1: left parent local (prev diag)
                float nb2 = p1;              // u=64: left parent = lane31 slot1

                float q0 = lae2p(p0 + blk0, nb0 + emt0);
                float q1 = lae2p(p1 + blk1, nb1 + emt1);
                float q2 = lae2p(p2 + blk2, nb2 + emt2);

                bool last = (d == d_end);
                f0 = last ? q0 : f0;
                f1 = last ? q1 : f1;
                f2 = last ? q2 : f2;

                p0 = q0; p1 = q1; p2 = q2;
            }
        }

        // Extract alpha[t_last][u_last] from snapshot of diagonal d_end.
        float af;
        if (u_last == 64)    af = __shfl_sync(0xffffffffu, f2, 31);
        else if (u_last & 1) af = __shfl_sync(0xffffffffu, f1, u_last >> 1);
        else                 af = __shfl_sync(0xffffffffu, f0, u_last >> 1);

        float fb = dbBase[d_end * Wn + u_last];   // blank lp2 at (t_last,u_last)
        if (lane == 0) out[b] = -(af + fb) * LN2;
        return;
    }

    // ======================= lse blocks =======================
    int idx  = (int)((blockIdx.x - Bn) * 8 + (threadIdx.x >> 5));
    int lane = threadIdx.x & 31;
    if (idx >= Bn * Tn * U1n) return;

    int b = idx & 7;                     // batch-interleaved
    int j = idx >> 3;                    // 0..8319, diagonal-major position
    int dd, u;
    diag_decode(j, dd, u);
    int t = dd - u;

    int Tl = logit_lengths[b];
    int Ul = target_lengths[b];
    if (t >= Tl || u > Ul) return;       // never read by the DP

    size_t rowIdx = (size_t)((b * Tn + t) * U1n + u);
    const float4* row = reinterpret_cast<const float4*>(logits) + rowIdx * (Vn / 4);
    float4 v[8];
#pragma unroll
    for (int jj = 0; jj < 8; jj++) v[jj] = row[jj * 32 + lane];

    float m = v[0].x;
#pragma unroll
    for (int jj = 0; jj < 8; jj++) {
        m = fmaxf(m, v[jj].x); m = fmaxf(m, v[jj].y);
        m = fmaxf(m, v[jj].z); m = fmaxf(m, v[jj].w);
    }
    float s = 0.0f;
#pragma unroll
    for (int jj = 0; jj < 8; jj++) {
        s += __expf(v[jj].x - m); s += __expf(v[jj].y - m);
        s += __expf(v[jj].z - m); s += __expf(v[jj].w - m);
    }

    // blank class = V-1: lives in v[7].w of lane 31.
    float blankv = __shfl_sync(0xffffffffu, v[7].w, 31);

#pragma unroll
    for (int off = 16; off; off >>= 1) {
        float om = __shfl_xor_sync(0xffffffffu, m, off);
        float os = __shfl_xor_sync(0xffffffffu, s, off);
        float nm = fmaxf(m, om);
        s = s * __expf(m - nm) + os * __expf(om - nm);
        m = nm;
    }
    float lse = m + __logf(s);

    if (lane == 0) {
        gD_blank[(b * DDn + dd) * Wn + u] = (blankv - lse) * LOG2E;
        if (u < Ul) {
            int tgt = targets[b * Un + u];
            gD_emit[(b * DDn + dd) * Wn + (u + 1)] =
                (logits[rowIdx * Vn + tgt] - lse) * LOG2E;
        }
        // Publish: release-ordered increment of this diagonal's counter.
        asm volatile("red.release.gpu.global.add.u32 [%0], 1;"
                     :: "l"(g_diag_ready + b * DDn + dd) : "memory");
    }
}

// ---------------------------------------------------------------------------
extern "C" void kernel_launch(void* const* d_in, const int* in_sizes, int n_in,
                              void* d_out, int out_size)
{
    const float* logits         = (const float*)d_in[0];
    const int*   targets        = (const int*)  d_in[1];
    const int*   logit_lengths  = (const int*)  d_in[2];
    const int*   target_lengths = (const int*)  d_in[3];
    float*       out            = (float*)      d_out;

    int rows       = Bn * Tn * U1n;                 // 66560 rows -> one warp each
    int lse_blocks = (rows + 7) / 8;                // 8320 blocks of 8 warps
    int blocks     = Bn + lse_blocks;               // DP blocks first (resident early)

    init_kernel<<<(Bn * DDn + 255) / 256, 256>>>();
    fused_kernel<<<blocks, 256>>>(logits, targets, logit_lengths, target_lengths, out);
}

// round 14
// speedup vs baseline: 1.2544x; 1.0049x over previous
#include <cuda_runtime.h>
#include <cstdint>
#include <cstddef>

// Problem constants (fixed by the dataset)
#define Bn   8
#define Tn   128
#define Un   64
#define U1n  65          // U+1
#define Vn   1024
// blank = V-1 (last class)

#define DDn  208         // padded diagonal count (max dd=190; prefetch reads to +2*GRP)
#define Wn   66          // padded diagonal width (u: 0..65)
#define GRP  4           // DP prefetch depth (diagonals)

#define LOG2E 1.4426950408889634f
#define LN2   0.6931471805599453f

// DIAGONAL-MAJOR scratch (base-2 log domain):
//   gD_blank[b][dd][u]   = lp2_blank(t,u),  dd = t+u
//   gD_emit [b][dd][u+1] = lp2_emit (t,u),  dd = t+u   (+1 shift so a float2 at
//                          [2l] yields (emit[.,2l-1], emit[.,2l]) per lane)
__device__ __align__(16) float gD_blank[Bn * DDn * Wn];
__device__ __align__(16) float gD_emit [Bn * DDn * Wn];
__device__ int g_diag_ready[Bn * DDn];   // #completed lse warps per (b, diagonal)

__device__ __forceinline__ float neg_inf() { return __int_as_float(0xff800000u); }

// Base-2 logaddexp via EX2 + deg-5 poly for log2(1+y); P(0)=0 keeps -inf algebra
// NaN-free (z clamped to -45 handles the both--inf NaN).
__device__ __forceinline__ float lae2p(float va, float vb) {
    const float C1 =  1.4419672f;
    const float C2 = -0.7096747f;
    const float C3 =  0.4176170f;
    const float C4 = -0.1962970f;
    const float C5 =  0.0463940f;
    float mx = fmaxf(va, vb);
    float mn = fminf(va, vb);
    float z  = fmaxf(mn - mx, -45.0f);
    float y;
    asm("ex2.approx.ftz.f32 %0, %1;" : "=f"(y) : "f"(z));
    float g = y * (C1 + y * (C2 + y * (C3 + y * (C4 + y * C5))));
    return mx + g;
}

// ---------------------------------------------------------------------------
__global__ void init_kernel() {
    int i = blockIdx.x * 256 + threadIdx.x;
    if (i < Bn * DDn) g_diag_ready[i] = 0;
}

// ---------------------------------------------------------------------------
// Fused kernel (single stream, graph-friendly).
//  blocks 0..7   : DP (warp0 = wavefront DP, warp1 = watermark poller)
//  blocks 8..    : lse rows in (t, b, u) order:
//                    - memory: 65-row (260 KB) contiguous runs per batch, 8
//                      interleaved sequential streams -> full DRAM/TLB locality
//                      (the R13 diag-interleaved order scattered 4 KB granules
//                      over 272 MB and halved bandwidth)
//                    - pipeline: every batch's frame t done at ~t/128 of lse
//                      time -> all DP blocks track the producer; only the
//                      final u_last diagonals (past t_last) run as a tail.
// __launch_bounds__(256,5) caps regs (~48) so lse keeps occupancy.
// ---------------------------------------------------------------------------
__global__ void __launch_bounds__(256, 5) fused_kernel(
    const float* __restrict__ logits,
    const int*   __restrict__ targets,
    const int*   __restrict__ logit_lengths,
    const int*   __restrict__ target_lengths,
    float*       __restrict__ out)
{
    // ======================= DP blocks =======================
    if (blockIdx.x < Bn) {
        __shared__ int s_wm;                 // highest fully-ready diagonal
        if (threadIdx.x == 0) s_wm = -1;
        __syncthreads();

        int b    = blockIdx.x;
        int wib  = threadIdx.x >> 5;
        int lane = threadIdx.x & 31;
        if (wib >= 2) return;

        int Tl = logit_lengths[b];
        int Ul = target_lengths[b];
        const int t_last = Tl - 1;
        const int u_last = Ul;
        const int d_end  = t_last + u_last;

        if (wib == 1) {
            // -------- poller: advance watermark, 32 diagonals per probe --------
            int w = -1;
            const int* cnt = g_diag_ready + b * DDn;
            while (w < d_end) {
                int dd = w + 1 + lane;
                int ok;
                if (dd <= d_end) {
                    int lo = max(0, dd - Ul);
                    int hi = min(t_last, dd);
                    int expect = hi - lo + 1;
                    int c;
                    asm volatile("ld.acquire.gpu.global.b32 %0, [%1];"
                                 : "=r"(c) : "l"(cnt + dd) : "memory");
                    ok = (c >= expect);
                } else ok = 1;
                unsigned bal = __ballot_sync(0xffffffffu, ok);
                int adv = (~bal == 0u) ? 32 : (__ffs(~bal) - 1);
                if (adv > 0) {
                    w += adv;
                    if (lane == 0) {
                        __threadfence_block();
                        *(volatile int*)&s_wm = w;
                    }
                } else {
                    __nanosleep(200);
                }
            }
            return;
        }

        // ---------------- DP warp ----------------
        const float NEG = neg_inf();
        const float* dbBase = gD_blank + b * DDn * Wn;
        const float* deBase = gD_emit  + b * DDn * Wn;
        const int src = (lane + 31) & 31;
        const bool l0 = (lane == 0);

        int wm_cache = -1;
        auto wait_wm = [&](int need) {
            if (wm_cache >= need) return;
            int v;
            do { v = *(volatile int*)&s_wm; } while (v < need);
            wm_cache = v;
            __threadfence_block();
        };

        float2 BA[GRP], EA[GRP];
        float  BU[GRP], EU[GRP];

        // Prologue: diagonals 0..GRP-1 feed iterations d = 1..GRP.
        wait_wm(min(GRP - 1, d_end));
#pragma unroll
        for (int k = 0; k < GRP; k++) {
            const float* pB = dbBase + k * Wn;
            const float* pE = deBase + k * Wn;
            BA[k] = *(const float2*)(pB + 2 * lane);
            EA[k] = *(const float2*)(pE + 2 * lane);
            BU[k] = pB[64];
            EU[k] = pE[64];
        }

        // Diagonal d = 0: only cell (0,0) (lane0 slot0) = 0.
        float p0 = l0 ? 0.0f : NEG;
        float p1 = NEG, p2 = NEG;
        float f0 = NEG, f1 = NEG, f2 = NEG;   // snapshot at d == d_end

        for (int g = 1; g <= d_end; g += GRP) {
            // Next group's prefetches touch diagonals up to g+2*GRP-2.
            wait_wm(min(g + 2 * GRP - 2, d_end));
#pragma unroll
            for (int k = 0; k < GRP; k++) {
                int d = g + k;
                float s1 = __shfl_sync(0xffffffffu, p1, src);

                float blk0 = BA[k].x, blk1 = BA[k].y, blk2 = BU[k];
                float emt0 = EA[k].x, emt1 = EA[k].y, emt2 = EU[k];

                // Prefetch diagonal d+GRP-1 (for iteration d+GRP) into slot k.
                {
                    int dd = g + k + GRP - 1;
                    const float* pB = dbBase + dd * Wn;
                    const float* pE = deBase + dd * Wn;
                    BA[k] = *(const float2*)(pB + 2 * lane);
                    EA[k] = *(const float2*)(pE + 2 * lane);
                    BU[k] = pB[64];
                    EU[k] = pE[64];
                }

                float nb0 = l0 ? NEG : s1;   // u=2l: left parent = lane l-1 odd col
                float nb1 = p0;              // u=2l+1: left parent local (prev diag)
                float nb2 = p1;              // u=64: left parent = lane31 slot1

                float q0 = lae2p(p0 + blk0, nb0 + emt0);
                float q1 = lae2p(p1 + blk1, nb1 + emt1);
                float q2 = lae2p(p2 + blk2, nb2 + emt2);

                bool last = (d == d_end);
                f0 = last ? q0 : f0;
                f1 = last ? q1 : f1;
                f2 = last ? q2 : f2;

                p0 = q0; p1 = q1; p2 = q2;
            }
        }

        // Extract alpha[t_last][u_last] from snapshot of diagonal d_end.
        float af;
        if (u_last == 64)    af = __shfl_sync(0xffffffffu, f2, 31);
        else if (u_last & 1) af = __shfl_sync(0xffffffffu, f1, u_last >> 1);
        else                 af = __shfl_sync(0xffffffffu, f0, u_last >> 1);

        float fb = dbBase[d_end * Wn + u_last];   // blank lp2 at (t_last,u_last)
        if (lane == 0) out[b] = -(af + fb) * LN2;
        return;
    }

    // ======================= lse blocks =======================
    int idx  = (int)((blockIdx.x - Bn) * 8 + (threadIdx.x >> 5));
    int lane = threadIdx.x & 31;
    if (idx >= Bn * Tn * U1n) return;

    // (t, b, u) order: all batches' frame t produced together, u-contiguous.
    int t = idx / (Bn * U1n);            // 0..127
    int r = idx - t * (Bn * U1n);
    int b = r / U1n;                     // 0..7
    int u = r - b * U1n;                 // 0..64

    int Tl = logit_lengths[b];
    int Ul = target_lengths[b];
    if (t >= Tl || u > Ul) return;       // never read by the DP

    size_t rowIdx = (size_t)((b * Tn + t) * U1n + u);
    const float4* row = reinterpret_cast<const float4*>(logits) + rowIdx * (Vn / 4);
    float4 v[8];
#pragma unroll
    for (int jj = 0; jj < 8; jj++) v[jj] = row[jj * 32 + lane];

    float m = v[0].x;
#pragma unroll
    for (int jj = 0; jj < 8; jj++) {
        m = fmaxf(m, v[jj].x); m = fmaxf(m, v[jj].y);
        m = fmaxf(m, v[jj].z); m = fmaxf(m, v[jj].w);
    }
    float s = 0.0f;
#pragma unroll
    for (int jj = 0; jj < 8; jj++) {
        s += __expf(v[jj].x - m); s += __expf(v[jj].y - m);
        s += __expf(v[jj].z - m); s += __expf(v[jj].w - m);
    }

    // blank class = V-1: lives in v[7].w of lane 31.
    float blankv = __shfl_sync(0xffffffffu, v[7].w, 31);

#pragma unroll
    for (int off = 16; off; off >>= 1) {
        float om = __shfl_xor_sync(0xffffffffu, m, off);
        float os = __shfl_xor_sync(0xffffffffu, s, off);
        float nm = fmaxf(m, om);
        s = s * __expf(m - nm) + os * __expf(om - nm);
        m = nm;
    }
    float lse = m + __logf(s);

    if (lane == 0) {
        int dd = t + u;
        gD_blank[(b * DDn + dd) * Wn + u] = (blankv - lse) * LOG2E;
        if (u < Ul) {
            int tgt = targets[b * Un + u];
            gD_emit[(b * DDn + dd) * Wn + (u + 1)] =
                (logits[rowIdx * Vn + tgt] - lse) * LOG2E;
        }
        // Publish: release-ordered increment of this diagonal's counter.
        asm volatile("red.release.gpu.global.add.u32 [%0], 1;"
                     :: "l"(g_diag_ready + b * DDn + dd) : "memory");
    }
}

// ---------------------------------------------------------------------------
extern "C" void kernel_launch(void* const* d_in, const int* in_sizes, int n_in,
                              void* d_out, int out_size)
{
    const float* logits         = (const float*)d_in[0];
    const int*   targets        = (const int*)  d_in[1];
    const int*   logit_lengths  = (const int*)  d_in[2];
    const int*   target_lengths = (const int*)  d_in[3];
    float*       out            = (float*)      d_out;

    int rows       = Bn * Tn * U1n;                 // 66560 rows -> one warp each
    int lse_blocks = (rows + 7) / 8;                // 8320 blocks of 8 warps
    int blocks     = Bn + lse_blocks;               // DP blocks first (resident early)

    init_kernel<<<(Bn * DDn + 255) / 256, 256>>>();
    fused_kernel<<<blocks, 256>>>(logits, targets, logit_lengths, target_lengths, out);
}

// round 15
// speedup vs baseline: 1.3850x; 1.1042x over previous
#include <cuda_runtime.h>
#include <cstdint>
#include <cstddef>

// Problem constants (fixed by the dataset)
#define Bn   8
#define Tn   128
#define Un   64
#define U1n  65          // U+1
#define Vn   1024
// blank = V-1 (last class)

#define LOG2E 1.4426950408889634f
#define LN2   0.6931471805599453f

// Scratch (BASE-2 log domain). g_blank stored PADDED to stride 66 so the DP
// preload is a flat vectorized copy.
__device__ __align__(16) float g_blank[Bn * Tn * 66];  // lp2[..., blank]
__device__ __align__(16) float g_emit [Bn * Tn * Un];  // lp2[..., targets[b,u]]

__device__ __forceinline__ float neg_inf() { return __int_as_float(0xff800000u); }

// Base-2 logaddexp: EX2 + degree-5 Estrin poly for log2(1+y), final mul+add
// folded into one FFMA. P(0)=0 keeps the -inf algebra NaN-free:
//   both -inf: mn-mx = NaN -> fmaxf(NaN,-45) = -45 -> y ~ 3e-14 -> mx stays -inf.
// Chain: FADDs(4) -> FMNMX(4) -> FADD(4) -> FMNMX(4) -> EX2(16) -> Estrin(12)
//        -> FFMA(4)  ~= 48 cyc.
__device__ __forceinline__ float lae2p(float va, float vb) {
    const float C1 =  1.4419672f;
    const float C2 = -0.7096747f;
    const float C3 =  0.4176170f;
    const float C4 = -0.1962970f;
    const float C5 =  0.0463940f;
    float mx = fmaxf(va, vb);
    float mn = fminf(va, vb);
    float z  = fmaxf(mn - mx, -45.0f);
    float y;
    asm("ex2.approx.ftz.f32 %0, %1;" : "=f"(y) : "f"(z));
    float y2 = y * y;
    float t1 = fmaf(C2, y, C1);
    float t2 = fmaf(C4, y, C3);
    float t3 = fmaf(y2, t2, t1);
    float y4 = y2 * y2;
    float P  = fmaf(y4, C5, t3);
    return fmaf(y, P, mx);
}

// ---------------------------------------------------------------------------
// Kernel 1: per-row log-sum-exp over V=1024; one warp per (b,t,u) row.
// Rows outside [0,T_l) x [0,U_l] skipped (~43% DRAM saved); runs at the
// LTS/DRAM cap. Outputs scaled by log2(e); blank stored stride-66 padded.
// (Unchanged from the 40.6us version — proven at the roofline.)
// ---------------------------------------------------------------------------
__global__ void __launch_bounds__(256) lse_kernel(
    const float* __restrict__ logits,
    const int*   __restrict__ targets,
    const int*   __restrict__ logit_lengths,
    const int*   __restrict__ target_lengths)
{
    int warp = (int)((blockIdx.x * 256u + threadIdx.x) >> 5);
    int lane = threadIdx.x & 31;
    if (warp >= Bn * Tn * U1n) return;

    int b   = warp / (Tn * U1n);
    int rem = warp - b * (Tn * U1n);
    int t   = rem / U1n;
    int u   = rem - t * U1n;

    int Tl = logit_lengths[b];
    int Ul = target_lengths[b];
    if (t >= Tl || u > Ul) return;   // never read by the DP

    const float4* row = reinterpret_cast<const float4*>(logits) + (size_t)warp * (Vn / 4);
    float4 v[8];
#pragma unroll
    for (int j = 0; j < 8; j++) v[j] = row[j * 32 + lane];

    float m = v[0].x;
#pragma unroll
    for (int j = 0; j < 8; j++) {
        m = fmaxf(m, v[j].x); m = fmaxf(m, v[j].y);
        m = fmaxf(m, v[j].z); m = fmaxf(m, v[j].w);
    }
    float s = 0.0f;
#pragma unroll
    for (int j = 0; j < 8; j++) {
        s += __expf(v[j].x - m); s += __expf(v[j].y - m);
        s += __expf(v[j].z - m); s += __expf(v[j].w - m);
    }

    // blank class = V-1: lives in v[7].w of lane 31.
    float blankv = __shfl_sync(0xffffffffu, v[7].w, 31);

#pragma unroll
    for (int off = 16; off; off >>= 1) {
        float om = __shfl_xor_sync(0xffffffffu, m, off);
        float os = __shfl_xor_sync(0xffffffffu, s, off);
        float nm = fmaxf(m, om);
        s = s * __expf(m - nm) + os * __expf(om - nm);
        m = nm;
    }
    float lse = m + __logf(s);

    if (lane == 0) {
        g_blank[(b * Tn + t) * 66 + u] = (blankv - lse) * LOG2E;
        if (u < Ul) {
            int tgt = targets[b * Un + u];
            g_emit[(b * Tn + t) * Un + u] = (logits[(size_t)warp * Vn + tgt] - lse) * LOG2E;
        }
    }
}

// ---------------------------------------------------------------------------
// Kernel 2: anti-diagonal wavefront DP, one warp per batch, base-2 log domain.
// Blocked ownership: lane l owns u=2l (slot0), u=2l+1 (slot1); u=64 = slot2
// (only when Ul==64 — otherwise the slot is skipped entirely: ~30% fewer
// instructions/diag). Lane0's missing left-neighbor handled by a dedicated
// -inf SMEM cell (stride-0 pointer) instead of a select on the shfl path.
// Boundary handling by construction (padded zero-filled SMEM, -inf regs).
// ---------------------------------------------------------------------------
#define PAD_LO   64
#define SROWS    256                    // rows -64..191
#define BLK_F    (SROWS * 66)           // 16896 floats
#define EMT_F    (SROWS * 64)           // 16384 floats
#define TAIL_F   68                     // pad for last prefetch + guard cell
#define TOT_F    (BLK_F + EMT_F + TAIL_F)
#define MINF_IDX (BLK_F + EMT_F + TAIL_F - 1)   // guard cell holding -inf

template <bool S2>
__device__ __forceinline__ void dp_loop(
    const float* s_blank0, const float* s_emit0, const float* minf_cell,
    int lane, int d_end, float& rp0, float& rp1, float& rp2)
{
    const float NEG = neg_inf();
    const int u0 = 2 * lane;
    const int u1 = 2 * lane + 1;
    const bool l0 = (lane == 0);
    const int src = (lane + 31) & 31;

    // Incremental SMEM pointers, positioned for d = 1.
    const float* pb0 = s_blank0 + (0 - u0) * 66 + u0;          // blank row d-1-u0
    const float* pe0 = l0 ? minf_cell
                          : s_emit0 + (1 - u0) * 64 + (u0 - 1); // emit row d-u0, col u0-1
    const int    e0s = l0 ? 0 : 64;
    const float* pb1 = s_blank0 + (0 - u1) * 66 + u1;
    const float* pe1 = s_emit0  + (1 - u1) * 64 + (u1 - 1);
    const float* pb2 = s_blank0 + (0 - 64) * 66 + 64;
    const float* pe2 = s_emit0  + (1 - 64) * 64 + 63;

    // Diagonal d = 0: only cell (0,0) (lane0 slot0) = 0.
    float p0 = l0 ? 0.0f : NEG;
    float p1 = NEG, p2 = NEG;

    // Prologue prefetch: values for d = 1.
    float blk0 = *pb0; pb0 += 66;
    float emt0 = *pe0; pe0 += e0s;
    float blk1 = *pb1; pb1 += 66;
    float emt1 = *pe1; pe1 += 64;
    float blk2 = 0.f, emt2 = 0.f;
    if (S2) { blk2 = *pb2; pb2 += 66; emt2 = *pe2; pe2 += 64; }

#pragma unroll 2
    for (int d = 1; d <= d_end; d++) {
        float s1 = __shfl_sync(0xffffffffu, p1, src);

        // Prefetch diagonal d+1 (independent of this iteration's chain).
        float blk0n = *pb0; pb0 += 66;
        float emt0n = *pe0; pe0 += e0s;
        float blk1n = *pb1; pb1 += 66;
        float emt1n = *pe1; pe1 += 64;
        float blk2n = 0.f, emt2n = 0.f;
        if (S2) { blk2n = *pb2; pb2 += 66; emt2n = *pe2; pe2 += 64; }

        // lane0: emt0 = -inf cell -> s1 + emt0 = -inf (no select needed).
        float q0 = lae2p(p0 + blk0, s1 + emt0);
        float q1 = lae2p(p1 + blk1, p0 + emt1);   // left parent local (prev diag)
        float q2;
        if (S2) q2 = lae2p(p2 + blk2, p1 + emt2); // u=64 left = lane31 slot1

        p0 = q0; p1 = q1;
        if (S2) p2 = q2;

        blk0 = blk0n; emt0 = emt0n;
        blk1 = blk1n; emt1 = emt1n;
        if (S2) { blk2 = blk2n; emt2 = emt2n; }
    }

    rp0 = p0; rp1 = p1; rp2 = p2;
}

__global__ void __launch_bounds__(128) dp_kernel(
    const int* __restrict__ logit_lengths,
    const int* __restrict__ target_lengths,
    float*     __restrict__ out)
{
    int b    = blockIdx.x;
    int tid  = threadIdx.x;
    int lane = tid & 31;
    int Tl   = logit_lengths[b];
    int Ul   = target_lengths[b];

    extern __shared__ float sh[];
    float* s_blank0 = sh + PAD_LO * 66;              // row-0 of blank
    float* s_emit0  = sh + BLK_F + PAD_LO * 64;      // row-0 of emit

    // Zero the whole padded region (vectorized), then set the -inf guard cell.
    {
        float4* sh4 = reinterpret_cast<float4*>(sh);
        const float4 z4 = make_float4(0.f, 0.f, 0.f, 0.f);
        for (int i = tid; i < TOT_F / 4; i += 128) sh4[i] = z4;
    }
    __syncthreads();

    // Flat vectorized preload (layouts match exactly: stride 66 / 64).
    {
        const float2* gb2 = reinterpret_cast<const float2*>(g_blank + b * Tn * 66);
        float2* sb2 = reinterpret_cast<float2*>(s_blank0);
        int n2 = Tl * 33;
        for (int i = tid; i < n2; i += 128) sb2[i] = gb2[i];

        const float4* ge4 = reinterpret_cast<const float4*>(g_emit + b * Tn * Un);
        float4* se4 = reinterpret_cast<float4*>(s_emit0);
        int n4 = Tl * 16;
        for (int i = tid; i < n4; i += 128) se4[i] = ge4[i];

        if (tid == 0) sh[MINF_IDX] = neg_inf();
    }
    __syncthreads();
    if (tid >= 32) return;               // warp 0 runs the DP alone

    const int t_last = Tl - 1;
    const int u_last = Ul;
    const int d_end  = t_last + u_last;

    float p0, p1, p2;
    float af;
    if (u_last == 64) {
        dp_loop<true >(s_blank0, s_emit0, sh + MINF_IDX, lane, d_end, p0, p1, p2);
        af = __shfl_sync(0xffffffffu, p2, 31);
    } else {
        dp_loop<false>(s_blank0, s_emit0, sh + MINF_IDX, lane, d_end, p0, p1, p2);
        if (u_last & 1) af = __shfl_sync(0xffffffffu, p1, u_last >> 1);
        else            af = __shfl_sync(0xffffffffu, p0, u_last >> 1);
    }

    if (lane == 0) {
        out[b] = -(af + s_blank0[t_last * 66 + u_last]) * LN2;
    }
}

// ---------------------------------------------------------------------------
extern "C" void kernel_launch(void* const* d_in, const int* in_sizes, int n_in,
                              void* d_out, int out_size)
{
    const float* logits         = (const float*)d_in[0];
    const int*   targets        = (const int*)  d_in[1];
    const int*   logit_lengths  = (const int*)  d_in[2];
    const int*   target_lengths = (const int*)  d_in[3];
    float*       out            = (float*)      d_out;

    const int smem_bytes = TOT_F * (int)sizeof(float);
    static int attr_set = 0;
    if (!attr_set) {
        cudaFuncSetAttribute(dp_kernel, cudaFuncAttributeMaxDynamicSharedMemorySize, smem_bytes);
        attr_set = 1;
    }

    int rows   = Bn * Tn * U1n;            // 66560 rows -> one warp each
    int blocks = (rows * 32 + 255) / 256;  // 8320 blocks

    lse_kernel<<<blocks, 256>>>(logits, targets, logit_lengths, target_lengths);
    dp_kernel<<<Bn, 128, smem_bytes>>>(logit_lengths, target_lengths, out);
}